// round 2
// baseline (speedup 1.0000x reference)
#include <cuda_runtime.h>
#include <math.h>

#define NROWS  262144
#define NCTA   8192          // 64 threads each -> 16384 warps, 16 rows/warp
#define NWARPS 16384
#define RU     4             // rows per warp-iteration (front-batched loads)

// Unified per-block weights, packed for f32x2 FMA.
// Layout: g_Wraw[lane*64 + o*16 + dp*2 + half] = M[j][2*dp+half][q*4+o]
// where lane = 4*j + q (j = block id, q = output quad), o = within-quad output,
// dp = d-pair index (d = 2*dp+half). Each consecutive float pair forms one
// 64-bit f32x2 weight operand.
__device__ float g_Wraw[32 * 4 * 8 * 2];

__global__ void bdla_prep(const float* __restrict__ W,
                          const float* __restrict__ s,
                          const float* __restrict__ U,
                          const float* __restrict__ V) {
    int e = threadIdx.x + blockIdx.x * blockDim.x;
    if (e >= 2048) return;
    int half = e & 1;
    int dp   = (e >> 1) & 7;
    int o    = (e >> 4) & 3;
    int lane = e >> 6;
    int j = lane >> 2, q = lane & 3;
    int d  = 2 * dp + half;     // input index within block
    int ob = q * 4 + o;         // output index within block
    float val;
    if (j == 0 || j == 3 || j == 6) {            // dense: y = x @ W^T
        int k = j / 3;
        val = W[k * 256 + ob * 16 + d];
    } else if (j == 1 || j == 4 || j == 7) {     // diagonal
        int k = (j - 1) / 3;
        val = (d == ob) ? s[k * 16 + d] : 0.0f;
    } else {                                     // lowrank: (V U^T)[d][o]
        int k = (j - 2) / 3;
        float acc = 0.0f;
        #pragma unroll
        for (int r = 0; r < 4; ++r)
            acc += V[k * 64 + d * 4 + r] * U[k * 64 + ob * 4 + r];
        val = acc;
    }
    g_Wraw[e] = val;
}

typedef unsigned long long ull;

__device__ __forceinline__ ull pk(float a, float b) {
    ull r; asm("mov.b64 %0, {%1,%2};" : "=l"(r) : "f"(a), "f"(b)); return r;
}
__device__ __forceinline__ void upk(ull p, float& a, float& b) {
    asm("mov.b64 {%0,%1}, %2;" : "=f"(a), "=f"(b) : "l"(p));
}
__device__ __forceinline__ ull ff2(ull a, ull b, ull c) {
    ull d; asm("fma.rn.f32x2 %0, %1, %2, %3;" : "=l"(d) : "l"(a), "l"(b), "l"(c));
    return d;
}

__global__ void __launch_bounds__(64, 10)
bdla_main(const float4* __restrict__ x, float4* __restrict__ y) {
    const int lane = threadIdx.x & 31;
    const int gw   = (blockIdx.x * 64 + threadIdx.x) >> 5;

    // 32 packed weight pairs = 64 regs; loaded once per warp (L2-resident).
    ull wp[32];
    {
        const ull* wsrc = ((const ull*)g_Wraw) + lane * 32;
        #pragma unroll
        for (int i = 0; i < 32; ++i) wp[i] = wsrc[i];
    }

    #pragma unroll 1
    for (int it = 0; it < NROWS / (NWARPS * RU); ++it) {
        const unsigned rbase = (unsigned)gw + (unsigned)(it * RU) * NWARPS;

        // Front-batch RU independent row loads (memory-level parallelism).
        float4 xs[RU];
        #pragma unroll
        for (int k = 0; k < RU; ++k)
            xs[k] = x[(rbase + (unsigned)k * NWARPS) * 32u + lane];

        #pragma unroll
        for (int k = 0; k < RU; ++k) {
            const float4 xv = xs[k];
            ull acc0 = 0ull, acc1 = 0ull, acc2 = 0ull, acc3 = 0ull;

            #pragma unroll
            for (int sb = 0; sb < 4; ++sb) {
                const int src = (lane & 28) + sb;   // lane holding d-quad sb of my block
                const float a0 = __shfl_sync(0xffffffffu, xv.x, src);
                const float a1 = __shfl_sync(0xffffffffu, xv.y, src);
                const float a2 = __shfl_sync(0xffffffffu, xv.z, src);
                const float a3 = __shfl_sync(0xffffffffu, xv.w, src);
                const ull p0 = pk(a0, a1);          // d = 4sb+0,4sb+1
                const ull p1 = pk(a2, a3);          // d = 4sb+2,4sb+3
                const int dp = 2 * sb;
                acc0 = ff2(p0, wp[0  + dp], acc0); acc0 = ff2(p1, wp[0  + dp + 1], acc0);
                acc1 = ff2(p0, wp[8  + dp], acc1); acc1 = ff2(p1, wp[8  + dp + 1], acc1);
                acc2 = ff2(p0, wp[16 + dp], acc2); acc2 = ff2(p1, wp[16 + dp + 1], acc2);
                acc3 = ff2(p0, wp[24 + dp], acc3); acc3 = ff2(p1, wp[24 + dp + 1], acc3);
            }

            float l0, h0, l1, h1, l2, h2, l3, h3;
            upk(acc0, l0, h0); upk(acc1, l1, h1);
            upk(acc2, l2, h2); upk(acc3, l3, h3);
            const float y0 = l0 + h0, y1 = l1 + h1, y2 = l2 + h2, y3 = l3 + h3;

            // L2 norm over the full 128-wide row (all 32 lanes).
            float ss = y0 * y0;
            ss = fmaf(y1, y1, ss); ss = fmaf(y2, y2, ss); ss = fmaf(y3, y3, ss);
            #pragma unroll
            for (int m = 16; m >= 1; m >>= 1)
                ss += __shfl_xor_sync(0xffffffffu, ss, m);
            const float inv = __fdividef(1.0f, sqrtf(ss) + 1e-8f);

            y[(rbase + (unsigned)k * NWARPS) * 32u + lane] =
                make_float4(y0 * inv, y1 * inv, y2 * inv, y3 * inv);
        }
    }
}

extern "C" void kernel_launch(void* const* d_in, const int* in_sizes, int n_in,
                              void* d_out, int out_size) {
    const float* x = (const float*)d_in[0];
    const float* W = (const float*)d_in[1];
    const float* s = (const float*)d_in[2];
    const float* U = (const float*)d_in[3];
    const float* V = (const float*)d_in[4];
    float* out = (float*)d_out;

    bdla_prep<<<8, 256>>>(W, s, U, V);
    bdla_main<<<NCTA, 64>>>((const float4*)x, (float4*)out);
}